// round 2
// baseline (speedup 1.0000x reference)
#include <cuda_runtime.h>
#include <cuda_bf16.h>

// Problem constants
#define NN 50000
#define EE 800000
#define F_IN 32
#define XCOLS 33          // F_IN + 1 (cell id column)
#define CELL_DIM 16
#define D_IN 48           // F_IN + CELL_DIM
#define CC 64
#define H0C 128           // H0 * C
#define NEG_SLOPE 0.2f

// ---------------- scratch (device globals; no allocation allowed) ----------
__device__ float    g_h0[NN * H0C];     // layer0 hidden [N, 2, 64]
__device__ float    g_as0[NN * 2];
__device__ float    g_ad0[NN * 2];
__device__ unsigned g_m0[NN * 2];       // orderable-uint max
__device__ float    g_den0[NN * 2];
__device__ float    g_acc0[NN * H0C];
__device__ float    g_h1[NN * CC];      // layer1 hidden [N, 64]
__device__ float    g_as1[NN];
__device__ float    g_ad1[NN];
__device__ unsigned g_m1[NN];
__device__ float    g_den1[NN];
__device__ float    g_acc1[NN * CC];

// ---------------- helpers --------------------------------------------------
__device__ __forceinline__ unsigned f2o(float f) {
    unsigned u = __float_as_uint(f);
    return (u & 0x80000000u) ? ~u : (u | 0x80000000u);
}
__device__ __forceinline__ float o2f(unsigned o) {
    return __uint_as_float((o & 0x80000000u) ? (o & 0x7fffffffu) : ~o);
}
__device__ __forceinline__ float lrelu(float e) {
    return e > 0.0f ? e : NEG_SLOPE * e;
}
__device__ __forceinline__ void red4(float* p, float4 v) {
    asm volatile("red.global.add.v4.f32 [%0], {%1,%2,%3,%4};"
                 :: "l"(p), "f"(v.x), "f"(v.y), "f"(v.z), "f"(v.w) : "memory");
}
__device__ __forceinline__ float warp_sum(float v) {
    v += __shfl_xor_sync(0xffffffffu, v, 16);
    v += __shfl_xor_sync(0xffffffffu, v, 8);
    v += __shfl_xor_sync(0xffffffffu, v, 4);
    v += __shfl_xor_sync(0xffffffffu, v, 2);
    v += __shfl_xor_sync(0xffffffffu, v, 1);
    return v;
}

// ---------------- K1: embed + concat + GEMM0 + attn logits + self max -----
// Block: 256 threads, 32 nodes per block.
__global__ void k_gemm0(const float* __restrict__ x,
                        const float* __restrict__ emb,
                        const float* __restrict__ W0,
                        const float* __restrict__ asw,
                        const float* __restrict__ adw) {
    __shared__ float sW[D_IN * H0C];   // 24 KB
    __shared__ float sH[32 * D_IN];    // 6 KB
    int t = threadIdx.x;
    int nb = blockIdx.x * 32;

    for (int i = t; i < D_IN * H0C; i += 256) sW[i] = W0[i];
    for (int i = t; i < 32 * D_IN; i += 256) {
        int n = i / D_IN, k = i % D_IN;
        int gn = nb + n;
        float v = 0.0f;
        if (gn < NN) {
            if (k < F_IN) v = x[gn * XCOLS + k];
            else {
                int cid = __float2int_rn(x[gn * XCOLS + F_IN]);
                v = emb[cid * CELL_DIM + (k - F_IN)];
            }
        }
        sH[n * D_IN + k] = v;
    }
    __syncthreads();

    int node = t >> 3;            // 0..31
    int jb   = (t & 7) * 16;      // 0..112
    float acc[16];
#pragma unroll
    for (int j = 0; j < 16; j++) acc[j] = 0.0f;
    for (int k = 0; k < D_IN; k++) {
        float a = sH[node * D_IN + k];
        const float* wr = &sW[k * H0C + jb];
#pragma unroll
        for (int j = 0; j < 16; j++) acc[j] += a * wr[j];
    }
    int gn = nb + node;
    bool ok = (gn < NN);
    if (ok) {
        float4* dst = (float4*)&g_h0[gn * H0C + jb];
#pragma unroll
        for (int q = 0; q < 4; q++)
            dst[q] = make_float4(acc[q*4], acc[q*4+1], acc[q*4+2], acc[q*4+3]);
    }
    // attention logit partial dots: head = jb>=64, cols jb&63 .. +15
    int head = jb >> 6;
    int cb = jb & 63;
    float ps = 0.0f, pd = 0.0f;
#pragma unroll
    for (int j = 0; j < 16; j++) {
        ps += acc[j] * asw[head * CC + cb + j];
        pd += acc[j] * adw[head * CC + cb + j];
    }
    // reduce over the 4 threads sharing (node, head): lanes 4m..4m+3
    ps += __shfl_xor_sync(0xffffffffu, ps, 1);
    ps += __shfl_xor_sync(0xffffffffu, ps, 2);
    pd += __shfl_xor_sync(0xffffffffu, pd, 1);
    pd += __shfl_xor_sync(0xffffffffu, pd, 2);
    if ((t & 3) == 0 && ok) {
        g_as0[gn * 2 + head] = ps;
        g_ad0[gn * 2 + head] = pd;
        g_m0[gn * 2 + head] = f2o(lrelu(ps + pd));   // self-loop seeds the max
    }
}

// ---------------- K2: edge max, layer 0 ------------------------------------
__global__ void k_max0(const int* __restrict__ src, const int* __restrict__ dst) {
    int i = blockIdx.x * blockDim.x + threadIdx.x;
    if (i >= EE) return;
    int s = src[i], d = dst[i];
#pragma unroll
    for (int h = 0; h < 2; h++) {
        float e = lrelu(g_as0[s * 2 + h] + g_ad0[d * 2 + h]);
        atomicMax(&g_m0[d * 2 + h], f2o(e));
    }
}

// ---------------- K3: node init (self loop), layer 0 -----------------------
__global__ void k_init0() {
    int i = blockIdx.x * blockDim.x + threadIdx.x;
    if (i >= NN * H0C) return;
    int n = i >> 7, c = i & 127, h = c >> 6;
    float e = lrelu(g_as0[n * 2 + h] + g_ad0[n * 2 + h]);
    float w = __expf(e - o2f(g_m0[n * 2 + h]));
    if ((c & 63) == 0) g_den0[n * 2 + h] = w;
    g_acc0[i] = g_h0[i] * w;
}

// ---------------- K4: edge messages, layer 0 (warp per edge) ---------------
__global__ void k_msg0(const int* __restrict__ src, const int* __restrict__ dst) {
    int e = blockIdx.x * 8 + (threadIdx.x >> 5);
    if (e >= EE) return;
    int lane = threadIdx.x & 31;
    int s = src[e], d = dst[e];
    int h = lane >> 4;
    float ee = lrelu(g_as0[s * 2 + h] + g_ad0[d * 2 + h]);
    float w = __expf(ee - o2f(g_m0[d * 2 + h]));
    if ((lane & 15) == 0) atomicAdd(&g_den0[d * 2 + h], w);
    float4 v = *(const float4*)&g_h0[s * H0C + lane * 4];
    v.x *= w; v.y *= w; v.z *= w; v.w *= w;
    red4(&g_acc0[d * H0C + lane * 4], v);
}

// ---------------- K5: finalize0 + LN + ELU + GEMM1 + logits1 ---------------
// Block: 256 threads = 8 warps, warp per node. W1 in smem.
__global__ void k_node1(const float* __restrict__ b0,
                        const float* __restrict__ lng,
                        const float* __restrict__ lnb,
                        const float* __restrict__ W1,
                        const float* __restrict__ as1w,
                        const float* __restrict__ ad1w) {
    __shared__ float sW1[CC * CC];   // 16 KB
    for (int i = threadIdx.x; i < CC * CC; i += 256) sW1[i] = W1[i];
    __syncthreads();
    int warp = threadIdx.x >> 5, lane = threadIdx.x & 31;
    int n = blockIdx.x * 8 + warp;
    if (n >= NN) return;

    float d0 = g_den0[n * 2], d1 = g_den0[n * 2 + 1];
    int c0 = lane, c1 = lane + 32;
    float v0 = 0.5f * (g_acc0[n * H0C + c0] / d0 + g_acc0[n * H0C + 64 + c0] / d1) + b0[c0];
    float v1 = 0.5f * (g_acc0[n * H0C + c1] / d0 + g_acc0[n * H0C + 64 + c1] / d1) + b0[c1];

    // LayerNorm over 64 channels
    float mean = warp_sum(v0 + v1) * (1.0f / 64.0f);
    v0 -= mean; v1 -= mean;
    float var = warp_sum(v0 * v0 + v1 * v1) * (1.0f / 64.0f);
    float r = rsqrtf(var + 1e-5f);
    v0 = v0 * r * lng[c0] + lnb[c0];
    v1 = v1 * r * lng[c1] + lnb[c1];
    // ELU
    v0 = v0 > 0.0f ? v0 : expm1f(v0);
    v1 = v1 > 0.0f ? v1 : expm1f(v1);

    // GEMM1: h1[j] = sum_k v[k] * W1[k][j]
    float a0 = 0.0f, a1 = 0.0f;
#pragma unroll
    for (int k = 0; k < 32; k++) {
        float vk = __shfl_sync(0xffffffffu, v0, k);
        a0 += vk * sW1[k * CC + c0];
        a1 += vk * sW1[k * CC + c1];
    }
#pragma unroll
    for (int k = 0; k < 32; k++) {
        float vk = __shfl_sync(0xffffffffu, v1, k);
        a0 += vk * sW1[(k + 32) * CC + c0];
        a1 += vk * sW1[(k + 32) * CC + c1];
    }
    g_h1[n * CC + c0] = a0;
    g_h1[n * CC + c1] = a1;

    float ps = warp_sum(a0 * as1w[c0] + a1 * as1w[c1]);
    float pd = warp_sum(a0 * ad1w[c0] + a1 * ad1w[c1]);
    if (lane == 0) {
        g_as1[n] = ps;
        g_ad1[n] = pd;
        g_m1[n] = f2o(lrelu(ps + pd));
    }
}

// ---------------- K6: edge max, layer 1 ------------------------------------
__global__ void k_max1(const int* __restrict__ src, const int* __restrict__ dst) {
    int i = blockIdx.x * blockDim.x + threadIdx.x;
    if (i >= EE) return;
    int s = src[i], d = dst[i];
    float e = lrelu(g_as1[s] + g_ad1[d]);
    atomicMax(&g_m1[d], f2o(e));
}

// ---------------- K7: node init (self loop), layer 1 -----------------------
__global__ void k_init1() {
    int i = blockIdx.x * blockDim.x + threadIdx.x;
    if (i >= NN * CC) return;
    int n = i >> 6, c = i & 63;
    float e = lrelu(g_as1[n] + g_ad1[n]);
    float w = __expf(e - o2f(g_m1[n]));
    if (c == 0) g_den1[n] = w;
    g_acc1[i] = g_h1[i] * w;
}

// ---------------- K8: edge messages, layer 1 (half-warp per edge) ----------
__global__ void k_msg1(const int* __restrict__ src, const int* __restrict__ dst) {
    int e = blockIdx.x * 16 + (threadIdx.x >> 4);
    if (e >= EE) return;
    int l = threadIdx.x & 15;
    int s = src[e], d = dst[e];
    float ee = lrelu(g_as1[s] + g_ad1[d]);
    float w = __expf(ee - o2f(g_m1[d]));
    if (l == 0) atomicAdd(&g_den1[d], w);
    float4 v = *(const float4*)&g_h1[s * CC + l * 4];
    v.x *= w; v.y *= w; v.z *= w; v.w *= w;
    red4(&g_acc1[d * CC + l * 4], v);
}

// ---------------- K9: final output -----------------------------------------
__global__ void k_final(float* __restrict__ out, const float* __restrict__ b1) {
    int i = blockIdx.x * blockDim.x + threadIdx.x;
    if (i >= NN * CC) return;
    int n = i >> 6, c = i & 63;
    out[i] = g_acc1[i] / g_den1[n] + b1[c];
}

// ---------------- launch ----------------------------------------------------
extern "C" void kernel_launch(void* const* d_in, const int* in_sizes, int n_in,
                              void* d_out, int out_size) {
    const float* x    = (const float*)d_in[0];
    const int*   ei   = (const int*)  d_in[1];
    const float* emb  = (const float*)d_in[2];
    const float* W0   = (const float*)d_in[3];
    const float* as0w = (const float*)d_in[4];
    const float* ad0w = (const float*)d_in[5];
    const float* b0   = (const float*)d_in[6];
    const float* lng  = (const float*)d_in[7];
    const float* lnb  = (const float*)d_in[8];
    const float* W1   = (const float*)d_in[9];
    const float* as1w = (const float*)d_in[10];
    const float* ad1w = (const float*)d_in[11];
    const float* b1   = (const float*)d_in[12];
    const int* src = ei;
    const int* dst = ei + EE;
    float* out = (float*)d_out;

    k_gemm0<<<(NN + 31) / 32, 256>>>(x, emb, W0, as0w, ad0w);
    k_max0<<<(EE + 255) / 256, 256>>>(src, dst);
    k_init0<<<(NN * H0C + 255) / 256, 256>>>();
    k_msg0<<<(EE + 7) / 8, 256>>>(src, dst);
    k_node1<<<(NN + 7) / 8, 256>>>(b0, lng, lnb, W1, as1w, ad1w);
    k_max1<<<(EE + 255) / 256, 256>>>(src, dst);
    k_init1<<<(NN * CC + 255) / 256, 256>>>();
    k_msg1<<<(EE + 15) / 16, 256>>>(src, dst);
    k_final<<<(NN * CC + 255) / 256, 256>>>(out, b1);
}

// round 3
// speedup vs baseline: 1.2145x; 1.2145x over previous
#include <cuda_runtime.h>
#include <cuda_bf16.h>

// Problem constants
#define NN 50000
#define EE 800000
#define F_IN 32
#define XCOLS 33
#define CELL_DIM 16
#define D_IN 48
#define CC 64
#define H0C 128
#define NEG_SLOPE 0.2f

// ---------------- scratch (device globals) ----------------
__device__ float    g_h0[NN * H0C];
__device__ float    g_as0[NN * 2];
__device__ float    g_ad0[NN * 2];
__device__ float    g_h1[NN * CC];
__device__ float    g_as1[NN];
__device__ float    g_ad1[NN];
__device__ unsigned g_deg[NN];
__device__ int      g_rowptr[NN + 1];
__device__ int      g_cursor[NN];
__device__ int      g_esrc[EE];

// ---------------- helpers ----------------
__device__ __forceinline__ float lrelu(float e) {
    return e > 0.0f ? e : NEG_SLOPE * e;
}
__device__ __forceinline__ float warp_sum(float v) {
    v += __shfl_xor_sync(0xffffffffu, v, 16);
    v += __shfl_xor_sync(0xffffffffu, v, 8);
    v += __shfl_xor_sync(0xffffffffu, v, 4);
    v += __shfl_xor_sync(0xffffffffu, v, 2);
    v += __shfl_xor_sync(0xffffffffu, v, 1);
    return v;
}

// ---------------- CSR build ----------------
__global__ void k_zero() {
    int i = blockIdx.x * blockDim.x + threadIdx.x;
    if (i < NN) g_deg[i] = 0u;
}
__global__ void k_hist(const int* __restrict__ dst) {
    int i = blockIdx.x * blockDim.x + threadIdx.x;
    if (i < EE) atomicAdd(&g_deg[dst[i]], 1u);
}
__global__ void k_scan() {
    __shared__ unsigned ssum[1024];
    const int IT = (NN + 1023) / 1024;   // 49
    int t = threadIdx.x;
    int base = t * IT;
    unsigned s = 0;
    for (int j = 0; j < IT; j++) {
        int idx = base + j;
        if (idx < NN) s += g_deg[idx];
    }
    ssum[t] = s;
    __syncthreads();
    for (int off = 1; off < 1024; off <<= 1) {
        unsigned v = (t >= off) ? ssum[t - off] : 0u;
        __syncthreads();
        ssum[t] += v;
        __syncthreads();
    }
    unsigned run = (t == 0) ? 0u : ssum[t - 1];
    for (int j = 0; j < IT; j++) {
        int idx = base + j;
        if (idx < NN) {
            g_rowptr[idx] = (int)run;
            g_cursor[idx] = (int)run;
            run += g_deg[idx];
        }
    }
    if (t == 0) g_rowptr[NN] = EE;
}
__global__ void k_scatter(const int* __restrict__ src, const int* __restrict__ dst) {
    int i = blockIdx.x * blockDim.x + threadIdx.x;
    if (i >= EE) return;
    int d = dst[i];
    int pos = atomicAdd(&g_cursor[d], 1);
    g_esrc[pos] = src[i];
}

// ---------------- K1: embed + concat + GEMM0 + attn logits ----------------
__global__ void k_gemm0(const float* __restrict__ x,
                        const float* __restrict__ emb,
                        const float* __restrict__ W0,
                        const float* __restrict__ asw,
                        const float* __restrict__ adw) {
    __shared__ float sW[D_IN * H0C];
    __shared__ float sH[32 * D_IN];
    int t = threadIdx.x;
    int nb = blockIdx.x * 32;

    for (int i = t; i < D_IN * H0C; i += 256) sW[i] = W0[i];
    for (int i = t; i < 32 * D_IN; i += 256) {
        int n = i / D_IN, k = i % D_IN;
        int gn = nb + n;
        float v = 0.0f;
        if (gn < NN) {
            if (k < F_IN) v = x[gn * XCOLS + k];
            else {
                int cid = __float2int_rn(x[gn * XCOLS + F_IN]);
                v = emb[cid * CELL_DIM + (k - F_IN)];
            }
        }
        sH[n * D_IN + k] = v;
    }
    __syncthreads();

    int node = t >> 3;
    int jb   = (t & 7) * 16;
    float acc[16];
#pragma unroll
    for (int j = 0; j < 16; j++) acc[j] = 0.0f;
    for (int k = 0; k < D_IN; k++) {
        float a = sH[node * D_IN + k];
        const float* wr = &sW[k * H0C + jb];
#pragma unroll
        for (int j = 0; j < 16; j++) acc[j] += a * wr[j];
    }
    int gn = nb + node;
    bool ok = (gn < NN);
    if (ok) {
        float4* dstp = (float4*)&g_h0[gn * H0C + jb];
#pragma unroll
        for (int q = 0; q < 4; q++)
            dstp[q] = make_float4(acc[q*4], acc[q*4+1], acc[q*4+2], acc[q*4+3]);
    }
    int head = jb >> 6;
    int cb = jb & 63;
    float ps = 0.0f, pd = 0.0f;
#pragma unroll
    for (int j = 0; j < 16; j++) {
        ps += acc[j] * asw[head * CC + cb + j];
        pd += acc[j] * adw[head * CC + cb + j];
    }
    ps += __shfl_xor_sync(0xffffffffu, ps, 1);
    ps += __shfl_xor_sync(0xffffffffu, ps, 2);
    pd += __shfl_xor_sync(0xffffffffu, pd, 1);
    pd += __shfl_xor_sync(0xffffffffu, pd, 2);
    if ((t & 3) == 0 && ok) {
        g_as0[gn * 2 + head] = ps;
        g_ad0[gn * 2 + head] = pd;
    }
}

// ---------------- K2: fused layer0 aggregate + LN + ELU + GEMM1 + logits1 --
// Block 256 = 8 warps, warp per node.
__global__ void k_layer0(const float* __restrict__ b0,
                         const float* __restrict__ lng,
                         const float* __restrict__ lnb,
                         const float* __restrict__ W1,
                         const float* __restrict__ as1w,
                         const float* __restrict__ ad1w) {
    __shared__ float sW1[CC * CC];      // 16 KB
    __shared__ float stage[8][CC];      // 2 KB
    for (int i = threadIdx.x; i < CC * CC; i += 256) sW1[i] = W1[i];
    __syncthreads();

    int warp = threadIdx.x >> 5, lane = threadIdx.x & 31;
    int n = blockIdx.x * 8 + warp;
    if (n >= NN) return;
    int h = lane >> 4;

    float2 adn = *(const float2*)&g_ad0[n * 2];
    float2 asn = *(const float2*)&g_as0[n * 2];
    float ad_h = h ? adn.y : adn.x;
    float e_self0 = lrelu(asn.x + adn.x);
    float e_self1 = lrelu(asn.y + adn.y);

    int start = g_rowptr[n], end = g_rowptr[n + 1];

    // pass 1: per-head max (self-loop seeds)
    float m0 = e_self0, m1 = e_self1;
    for (int j = start + lane; j < end; j += 32) {
        int s = g_esrc[j];
        float2 as = *(const float2*)&g_as0[s * 2];
        m0 = fmaxf(m0, lrelu(as.x + adn.x));
        m1 = fmaxf(m1, lrelu(as.y + adn.y));
    }
#pragma unroll
    for (int o = 16; o; o >>= 1) {
        m0 = fmaxf(m0, __shfl_xor_sync(0xffffffffu, m0, o));
        m1 = fmaxf(m1, __shfl_xor_sync(0xffffffffu, m1, o));
    }
    float m_h = h ? m1 : m0;

    // init with self loop
    float wself = __expf((h ? e_self1 : e_self0) - m_h);
    float4 acc = *(const float4*)&g_h0[n * H0C + lane * 4];
    acc.x *= wself; acc.y *= wself; acc.z *= wself; acc.w *= wself;
    float den = ((lane & 15) == 0) ? wself : 0.0f;

    // pass 2: gather (unroll 2 for MLP)
    int j = start;
    for (; j + 1 < end; j += 2) {
        int s0 = g_esrc[j], s1 = g_esrc[j + 1];
        float w0 = __expf(lrelu(g_as0[s0 * 2 + h] + ad_h) - m_h);
        float w1 = __expf(lrelu(g_as0[s1 * 2 + h] + ad_h) - m_h);
        float4 v0 = *(const float4*)&g_h0[s0 * H0C + lane * 4];
        float4 v1 = *(const float4*)&g_h0[s1 * H0C + lane * 4];
        acc.x += v0.x * w0 + v1.x * w1;
        acc.y += v0.y * w0 + v1.y * w1;
        acc.z += v0.z * w0 + v1.z * w1;
        acc.w += v0.w * w0 + v1.w * w1;
        if ((lane & 15) == 0) den += w0 + w1;
    }
    if (j < end) {
        int s0 = g_esrc[j];
        float w0 = __expf(lrelu(g_as0[s0 * 2 + h] + ad_h) - m_h);
        float4 v0 = *(const float4*)&g_h0[s0 * H0C + lane * 4];
        acc.x += v0.x * w0; acc.y += v0.y * w0;
        acc.z += v0.z * w0; acc.w += v0.w * w0;
        if ((lane & 15) == 0) den += w0;
    }

    // normalize by own head's denom
    float den0 = __shfl_sync(0xffffffffu, den, 0);
    float den1 = __shfl_sync(0xffffffffu, den, 16);
    float inv = 1.0f / (h ? den1 : den0);
    acc.x *= inv; acc.y *= inv; acc.z *= inv; acc.w *= inv;

    // head mean: lane l (0-15) pairs with lane l+16
    float px = __shfl_xor_sync(0xffffffffu, acc.x, 16);
    float py = __shfl_xor_sync(0xffffffffu, acc.y, 16);
    float pz = __shfl_xor_sync(0xffffffffu, acc.z, 16);
    float pw = __shfl_xor_sync(0xffffffffu, acc.w, 16);
    if (lane < 16) {
        stage[warp][lane * 4 + 0] = 0.5f * (acc.x + px);
        stage[warp][lane * 4 + 1] = 0.5f * (acc.y + py);
        stage[warp][lane * 4 + 2] = 0.5f * (acc.z + pz);
        stage[warp][lane * 4 + 3] = 0.5f * (acc.w + pw);
    }
    __syncwarp();

    int c0 = lane, c1 = lane + 32;
    float v0 = stage[warp][c0] + b0[c0];
    float v1 = stage[warp][c1] + b0[c1];

    // LayerNorm
    float mean = warp_sum(v0 + v1) * (1.0f / 64.0f);
    v0 -= mean; v1 -= mean;
    float var = warp_sum(v0 * v0 + v1 * v1) * (1.0f / 64.0f);
    float r = rsqrtf(var + 1e-5f);
    v0 = v0 * r * lng[c0] + lnb[c0];
    v1 = v1 * r * lng[c1] + lnb[c1];
    v0 = v0 > 0.0f ? v0 : expm1f(v0);
    v1 = v1 > 0.0f ? v1 : expm1f(v1);

    // GEMM1
    float a0 = 0.0f, a1 = 0.0f;
#pragma unroll
    for (int k = 0; k < 32; k++) {
        float vk = __shfl_sync(0xffffffffu, v0, k);
        a0 += vk * sW1[k * CC + c0];
        a1 += vk * sW1[k * CC + c1];
    }
#pragma unroll
    for (int k = 0; k < 32; k++) {
        float vk = __shfl_sync(0xffffffffu, v1, k);
        a0 += vk * sW1[(k + 32) * CC + c0];
        a1 += vk * sW1[(k + 32) * CC + c1];
    }
    g_h1[n * CC + c0] = a0;
    g_h1[n * CC + c1] = a1;

    float ps = warp_sum(a0 * as1w[c0] + a1 * as1w[c1]);
    float pd = warp_sum(a0 * ad1w[c0] + a1 * ad1w[c1]);
    if (lane == 0) {
        g_as1[n] = ps;
        g_ad1[n] = pd;
    }
}

// ---------------- K3: fused layer1 aggregate + output ----------------------
// Block 256 = 16 half-warps, half-warp per node.
__global__ void k_layer1(float* __restrict__ out, const float* __restrict__ b1) {
    int hw = threadIdx.x >> 4;
    int l  = threadIdx.x & 15;
    int n = blockIdx.x * 16 + hw;
    if (n >= NN) return;

    float adn = g_ad1[n];
    float e_self = lrelu(g_as1[n] + adn);
    int start = g_rowptr[n], end = g_rowptr[n + 1];

    // pass 1: max
    float m = e_self;
    for (int j = start + l; j < end; j += 16)
        m = fmaxf(m, lrelu(g_as1[g_esrc[j]] + adn));
#pragma unroll
    for (int o = 8; o; o >>= 1)
        m = fmaxf(m, __shfl_xor_sync(0xffffffffu, m, o));

    float wself = __expf(e_self - m);
    float4 acc = *(const float4*)&g_h1[n * CC + l * 4];
    acc.x *= wself; acc.y *= wself; acc.z *= wself; acc.w *= wself;
    float den = (l == 0) ? wself : 0.0f;

    int j = start;
    for (; j + 1 < end; j += 2) {
        int s0 = g_esrc[j], s1 = g_esrc[j + 1];
        float w0 = __expf(lrelu(g_as1[s0] + adn) - m);
        float w1 = __expf(lrelu(g_as1[s1] + adn) - m);
        float4 v0 = *(const float4*)&g_h1[s0 * CC + l * 4];
        float4 v1 = *(const float4*)&g_h1[s1 * CC + l * 4];
        acc.x += v0.x * w0 + v1.x * w1;
        acc.y += v0.y * w0 + v1.y * w1;
        acc.z += v0.z * w0 + v1.z * w1;
        acc.w += v0.w * w0 + v1.w * w1;
        if (l == 0) den += w0 + w1;
    }
    if (j < end) {
        int s0 = g_esrc[j];
        float w0 = __expf(lrelu(g_as1[s0] + adn) - m);
        float4 v0 = *(const float4*)&g_h1[s0 * CC + l * 4];
        acc.x += v0.x * w0; acc.y += v0.y * w0;
        acc.z += v0.z * w0; acc.w += v0.w * w0;
        if (l == 0) den += w0;
    }

    den = __shfl_sync(0xffffffffu, den, threadIdx.x & 16);
    float invd = 1.0f / den;
    float4 o4;
    o4.x = acc.x * invd + b1[l * 4 + 0];
    o4.y = acc.y * invd + b1[l * 4 + 1];
    o4.z = acc.z * invd + b1[l * 4 + 2];
    o4.w = acc.w * invd + b1[l * 4 + 3];
    *(float4*)&out[n * CC + l * 4] = o4;
}

// ---------------- launch ----------------------------------------------------
extern "C" void kernel_launch(void* const* d_in, const int* in_sizes, int n_in,
                              void* d_out, int out_size) {
    const float* x    = (const float*)d_in[0];
    const int*   ei   = (const int*)  d_in[1];
    const float* emb  = (const float*)d_in[2];
    const float* W0   = (const float*)d_in[3];
    const float* as0w = (const float*)d_in[4];
    const float* ad0w = (const float*)d_in[5];
    const float* b0   = (const float*)d_in[6];
    const float* lng  = (const float*)d_in[7];
    const float* lnb  = (const float*)d_in[8];
    const float* W1   = (const float*)d_in[9];
    const float* as1w = (const float*)d_in[10];
    const float* ad1w = (const float*)d_in[11];
    const float* b1   = (const float*)d_in[12];
    const int* src = ei;
    const int* dst = ei + EE;
    float* out = (float*)d_out;

    // CSR build (by dst)
    k_zero<<<(NN + 255) / 256, 256>>>();
    k_hist<<<(EE + 255) / 256, 256>>>(dst);
    k_scan<<<1, 1024>>>();
    k_scatter<<<(EE + 255) / 256, 256>>>(src, dst);

    // node features + layer-0 projections
    k_gemm0<<<(NN + 31) / 32, 256>>>(x, emb, W0, as0w, ad0w);

    // fused layers
    k_layer0<<<(NN + 7) / 8, 256>>>(b0, lng, lnb, W1, as1w, ad1w);
    k_layer1<<<(NN + 15) / 16, 256>>>(out, b1);
}